// round 2
// baseline (speedup 1.0000x reference)
#include <cuda_runtime.h>
#include <cstdint>

#define NB 16
#define NC 64          // C_IN == C_OUT == 64
#define VIN 40962
#define VOUT 163842

// Scratch: y[b][u][o], channel-contiguous rows (256B per vertex). ~168 MB.
__device__ float g_y[(size_t)NB * VIN * NC];
// 1 if idx buffer is int64, 0 if int32.
__device__ int g_idx_is64;

// ---------------------------------------------------------------------------
// Index dtype detection: int64 data has zero high words (indices < 2^31).
// ---------------------------------------------------------------------------
__global__ void detect_idx_dtype(const int* __restrict__ idx32) {
    int all_odd_zero = 1;
#pragma unroll
    for (int k = 0; k < 8; k++)
        if (idx32[2 * k + 1] != 0) all_odd_zero = 0;
    g_idx_is64 = all_odd_zero;
}

// ---------------------------------------------------------------------------
// Stage 1: y[b,u,o] = sum_c x[b,c,u] * W[o,c]
// Block = 256 threads, tile 64 u x 64 o, full K=64.
// ---------------------------------------------------------------------------
__global__ __launch_bounds__(256)
void stage1_gemm(const float* __restrict__ x, const float* __restrict__ W) {
    __shared__ float xs[64][64];   // [c][u]
    __shared__ float wt[64][68];   // [c][o] transposed W, padded

    const int b   = blockIdx.y;
    const int u0  = blockIdx.x * 64;
    const int tid = threadIdx.x;

    for (int i = tid; i < 64 * 64; i += 256) {
        int o = i >> 6, c = i & 63;
        wt[c][o] = W[o * 64 + c];
    }
    const float* xb = x + (size_t)b * NC * VIN;
    for (int i = tid; i < 64 * 64; i += 256) {
        int c = i >> 6, u = i & 63;
        int ug = u0 + u;
        xs[c][u] = (ug < VIN) ? xb[(size_t)c * VIN + ug] : 0.0f;
    }
    __syncthreads();

    const int tx = tid & 15;   // u quad
    const int ty = tid >> 4;   // o quad

    float acc[4][4];
#pragma unroll
    for (int i = 0; i < 4; i++)
#pragma unroll
        for (int j = 0; j < 4; j++) acc[i][j] = 0.0f;

#pragma unroll
    for (int c = 0; c < 64; c++) {
        float4 xv = *(const float4*)&xs[c][tx * 4];
        float4 wv = *(const float4*)&wt[c][ty * 4];
        float xa[4] = {xv.x, xv.y, xv.z, xv.w};
        float wa[4] = {wv.x, wv.y, wv.z, wv.w};
#pragma unroll
        for (int i = 0; i < 4; i++)
#pragma unroll
            for (int j = 0; j < 4; j++) acc[i][j] = fmaf(xa[i], wa[j], acc[i][j]);
    }

    float* yb = g_y + (size_t)b * VIN * NC;
#pragma unroll
    for (int i = 0; i < 4; i++) {
        int ug = u0 + tx * 4 + i;
        if (ug < VIN) {
            float4 v = make_float4(acc[i][0], acc[i][1], acc[i][2], acc[i][3]);
            *(float4*)&yb[(size_t)ug * NC + ty * 4] = v;
        }
    }
}

// ---------------------------------------------------------------------------
// Stage 2: out[b,o,v] = 0.5*(y[b,i0(v),o] + y[b,i1(v),o]) + bias[o]
// Block = 256 threads, 64-vertex tile; transpose via smem for coalesced writes.
// ---------------------------------------------------------------------------
__global__ __launch_bounds__(256)
void stage2_gather(const void* __restrict__ idx_raw,
                   const float* __restrict__ bias,
                   float* __restrict__ out) {
    __shared__ float t[64][65];
    __shared__ float bs[64];

    const int b   = blockIdx.y;
    const int v0  = blockIdx.x * 64;
    const int tid = threadIdx.x;
    const int is64 = g_idx_is64;

    if (tid < 64) bs[tid] = bias[tid];

    const float* yb = g_y + (size_t)b * VIN * NC;

    // Gather phase: 4 threads per vertex, 16 channels each via float4.
    {
        const int vl = tid >> 2;
        const int q  = tid & 3;
        const int v  = v0 + vl;
        if (v < VOUT) {
            long long i0, i1;
            if (is64) {
                const long long* p = (const long long*)idx_raw + (size_t)v * 2;
                i0 = p[0]; i1 = p[1];
            } else {
                const int* p = (const int*)idx_raw + (size_t)v * 2;
                i0 = p[0]; i1 = p[1];
            }
            // Clamp defensively: wrong decode -> wrong answer, not IMA.
            i0 = i0 < 0 ? 0 : (i0 >= VIN ? VIN - 1 : i0);
            i1 = i1 < 0 ? 0 : (i1 >= VIN ? VIN - 1 : i1);
            const float* r0 = yb + (size_t)i0 * NC;
            const float* r1 = yb + (size_t)i1 * NC;
#pragma unroll
            for (int it = 0; it < 4; it++) {
                int c = it * 16 + q * 4;
                float4 a  = *(const float4*)&r0[c];
                float4 c2 = *(const float4*)&r1[c];
                t[vl][c + 0] = 0.5f * (a.x + c2.x);
                t[vl][c + 1] = 0.5f * (a.y + c2.y);
                t[vl][c + 2] = 0.5f * (a.z + c2.z);
                t[vl][c + 3] = 0.5f * (a.w + c2.w);
            }
        }
    }
    __syncthreads();

    // Write phase: coalesced along v.
    {
        const int lv = tid & 63;
        const int og = tid >> 6;
        const int vg = v0 + lv;
        if (vg < VOUT) {
            float* ob = out + (size_t)b * NC * VOUT + (size_t)vg;
#pragma unroll
            for (int i = 0; i < 16; i++) {
                int o = og * 16 + i;
                ob[(size_t)o * VOUT] = t[lv][o] + bs[o];
            }
        }
    }
}

// ---------------------------------------------------------------------------
extern "C" void kernel_launch(void* const* d_in, const int* in_sizes, int n_in,
                              void* d_out, int out_size) {
    // Resolve inputs by unique element counts (robust to ordering).
    const float* x = nullptr;
    const void*  idx = nullptr;
    const float* W = nullptr;
    const float* bias = nullptr;
    for (int i = 0; i < n_in; i++) {
        switch (in_sizes[i]) {
            case 41945088: x    = (const float*)d_in[i]; break;  // 16*64*40962
            case 327684:   idx  = d_in[i];               break;  // 163842*2
            case 4096:     W    = (const float*)d_in[i]; break;  // 64*64
            case 64:       bias = (const float*)d_in[i]; break;  // 64
            default: break;
        }
    }
    float* out = (float*)d_out;
    (void)out_size;

    detect_idx_dtype<<<1, 1>>>((const int*)idx);

    dim3 g1((VIN + 63) / 64, NB);
    stage1_gemm<<<g1, 256>>>(x, W);

    dim3 g2((VOUT + 63) / 64, NB);
    stage2_gather<<<g2, 256>>>(idx, bias, out);
}

// round 3
// speedup vs baseline: 1.3438x; 1.3438x over previous
#include <cuda_runtime.h>
#include <cstdint>

#define NB 16
#define NC 64          // C_IN == C_OUT == 64
#define VIN 40962
#define VOUT 163842

typedef unsigned long long ull;

// Scratch: y[b][u][o], channel-contiguous rows (256B per vertex). ~168 MB.
__device__ float g_y[(size_t)NB * VIN * NC];
// W transposed once: g_wt[c*64+o] = W[o*64+c]
__device__ float g_wt[NC * NC];
// 1 if idx buffer is int64, 0 if int32.
__device__ int g_idx_is64;

// ---------------------------------------------------------------------------
// Prep: detect idx dtype (int64 has zero high words) + transpose W once.
// ---------------------------------------------------------------------------
__global__ void prep_kernel(const float* __restrict__ W,
                            const int* __restrict__ idx32) {
    const int tid = threadIdx.x;
    if (tid == 0) {
        int all_odd_zero = 1;
#pragma unroll
        for (int k = 0; k < 8; k++)
            if (idx32[2 * k + 1] != 0) all_odd_zero = 0;
        g_idx_is64 = all_odd_zero;
    }
    for (int i = tid; i < NC * NC; i += blockDim.x) {
        int c = i >> 6, o = i & 63;
        g_wt[c * 64 + o] = W[o * 64 + c];
    }
}

// ---------------------------------------------------------------------------
// Stage 1: y[b,u,o] = sum_c x[b,c,u] * W[o,c]
// Tile 128u x 64o, 128 threads, each thread 8u x 8o via packed f32x2 FMA.
// u-pairs come packed for free from double2 smem loads; w is broadcast.
// ---------------------------------------------------------------------------
__global__ __launch_bounds__(128)
void stage1_gemm(const float* __restrict__ x) {
    __shared__ float xs[64][128];   // [c][u]  32 KB
    __shared__ float ws[64][64];    // [c][o]  16 KB (reads are broadcast; no pad needed)

    const int b   = blockIdx.y;
    const int u0  = blockIdx.x * 128;
    const int tid = threadIdx.x;
    const int uo  = tid & 15;       // u-octet: u = uo*8 + 0..7
    const int og  = tid >> 4;       // o-octet: o = og*8 + 0..7

    // Coalesced, conflict-free W-tile load from pre-transposed copy.
#pragma unroll
    for (int i = tid; i < NC * NC; i += 128)
        ((float*)ws)[i] = g_wt[i];

    // x tile load (float2: rows are only 8B-aligned since VIN*4 % 16 == 8).
    const float* xb = x + (size_t)b * NC * VIN + u0;
    if (u0 + 128 <= VIN) {
#pragma unroll
        for (int i = tid; i < 64 * 64; i += 128) {
            int c = i >> 6, j = i & 63;
            float2 v = __ldcs((const float2*)(xb + (size_t)c * VIN + j * 2));
            *(float2*)&xs[c][j * 2] = v;
        }
    } else {
        for (int i = tid; i < 64 * 128; i += 128) {
            int c = i >> 7, u = i & 127;
            xs[c][u] = (u0 + u < VIN) ? __ldcs(xb + (size_t)c * VIN + u) : 0.0f;
        }
    }
    __syncthreads();

    // Accumulators: acc[ip][j] = packed f32x2 over (u = 2ip, 2ip+1), o = og*8+j
    ull acc[4][8];
#pragma unroll
    for (int ip = 0; ip < 4; ip++)
#pragma unroll
        for (int j = 0; j < 8; j++) acc[ip][j] = 0ull;

#pragma unroll 16
    for (int c = 0; c < 64; c++) {
        // 8 u-values as 4 packed pairs (two 16B smem loads, 32B-aligned)
        double2 xv0 = *(const double2*)&xs[c][uo * 8];
        double2 xv1 = *(const double2*)&xs[c][uo * 8 + 4];
        ull xp[4];
        xp[0] = __double_as_longlong(xv0.x);
        xp[1] = __double_as_longlong(xv0.y);
        xp[2] = __double_as_longlong(xv1.x);
        xp[3] = __double_as_longlong(xv1.y);

        float4 w0 = *(const float4*)&ws[c][og * 8];
        float4 w1 = *(const float4*)&ws[c][og * 8 + 4];
        float wf[8] = {w0.x, w0.y, w0.z, w0.w, w1.x, w1.y, w1.z, w1.w};

#pragma unroll
        for (int j = 0; j < 8; j++) {
            ull wp;
            asm("mov.b64 %0, {%1, %1};" : "=l"(wp) : "f"(wf[j]));
#pragma unroll
            for (int ip = 0; ip < 4; ip++)
                asm("fma.rn.f32x2 %0, %1, %2, %0;"
                    : "+l"(acc[ip][j]) : "l"(xp[ip]), "l"(wp));
        }
    }

    // Epilogue: y[b][u][o], 8 rows x 8 o per thread (two float4 stores/row).
    float* yb = g_y + (size_t)b * VIN * NC;
#pragma unroll
    for (int du = 0; du < 8; du++) {
        int ug = u0 + uo * 8 + du;
        if (ug < VIN) {
            const int ip = du >> 1;
            const int hi = du & 1;
            union { ull u; float2 f; } cv;
            float r[8];
#pragma unroll
            for (int j = 0; j < 8; j++) {
                cv.u = acc[ip][j];
                r[j] = hi ? cv.f.y : cv.f.x;
            }
            float4 a = make_float4(r[0], r[1], r[2], r[3]);
            float4 c2 = make_float4(r[4], r[5], r[6], r[7]);
            float* row = &yb[(size_t)ug * NC + og * 8];
            *(float4*)row = a;
            *(float4*)(row + 4) = c2;
        }
    }
}

// ---------------------------------------------------------------------------
// Stage 2: out[b,o,v] = 0.5*(y[b,i0(v),o] + y[b,i1(v),o]) + bias[o]
// ---------------------------------------------------------------------------
__global__ __launch_bounds__(256)
void stage2_gather(const void* __restrict__ idx_raw,
                   const float* __restrict__ bias,
                   float* __restrict__ out) {
    __shared__ float t[64][65];
    __shared__ float bs[64];

    const int b   = blockIdx.y;
    const int v0  = blockIdx.x * 64;
    const int tid = threadIdx.x;
    const int is64 = g_idx_is64;

    if (tid < 64) bs[tid] = bias[tid];

    const float* yb = g_y + (size_t)b * VIN * NC;

    // Gather phase: 4 threads per vertex, 16 channels each via float4.
    {
        const int vl = tid >> 2;
        const int q  = tid & 3;
        const int v  = v0 + vl;
        if (v < VOUT) {
            long long i0, i1;
            if (is64) {
                const long long* p = (const long long*)idx_raw + (size_t)v * 2;
                i0 = p[0]; i1 = p[1];
            } else {
                const int* p = (const int*)idx_raw + (size_t)v * 2;
                i0 = p[0]; i1 = p[1];
            }
            i0 = i0 < 0 ? 0 : (i0 >= VIN ? VIN - 1 : i0);
            i1 = i1 < 0 ? 0 : (i1 >= VIN ? VIN - 1 : i1);
            const float* r0 = yb + (size_t)i0 * NC;
            const float* r1 = yb + (size_t)i1 * NC;
#pragma unroll
            for (int it = 0; it < 4; it++) {
                int c = it * 16 + q * 4;
                float4 a  = *(const float4*)&r0[c];
                float4 c2 = *(const float4*)&r1[c];
                t[vl][c + 0] = 0.5f * (a.x + c2.x);
                t[vl][c + 1] = 0.5f * (a.y + c2.y);
                t[vl][c + 2] = 0.5f * (a.z + c2.z);
                t[vl][c + 3] = 0.5f * (a.w + c2.w);
            }
        }
    }
    __syncthreads();

    // Write phase: coalesced along v; streaming stores (out never re-read).
    {
        const int lv = tid & 63;
        const int og = tid >> 6;
        const int vg = v0 + lv;
        if (vg < VOUT) {
            float* ob = out + (size_t)b * NC * VOUT + (size_t)vg;
#pragma unroll
            for (int i = 0; i < 16; i++) {
                int o = og * 16 + i;
                __stcs(&ob[(size_t)o * VOUT], t[lv][o] + bs[o]);
            }
        }
    }
}

// ---------------------------------------------------------------------------
extern "C" void kernel_launch(void* const* d_in, const int* in_sizes, int n_in,
                              void* d_out, int out_size) {
    const float* x = nullptr;
    const void*  idx = nullptr;
    const float* W = nullptr;
    const float* bias = nullptr;
    for (int i = 0; i < n_in; i++) {
        switch (in_sizes[i]) {
            case 41945088: x    = (const float*)d_in[i]; break;  // 16*64*40962
            case 327684:   idx  = d_in[i];               break;  // 163842*2
            case 4096:     W    = (const float*)d_in[i]; break;  // 64*64
            case 64:       bias = (const float*)d_in[i]; break;  // 64
            default: break;
        }
    }
    float* out = (float*)d_out;
    (void)out_size;

    prep_kernel<<<1, 256>>>(W, (const int*)idx);

    dim3 g1((VIN + 127) / 128, NB);
    stage1_gemm<<<g1, 128>>>(x);

    dim3 g2((VOUT + 63) / 64, NB);
    stage2_gather<<<g2, 256>>>(idx, bias, out);
}